// round 4
// baseline (speedup 1.0000x reference)
#include <cuda_runtime.h>
#include <cstdint>
#include <cstddef>

#define Hd 128
#define FEAT 512
#define NSRC0 50000
#define NDST0 20000
#define NDST1 4096
#define E0 320000
#define E1 65536

#define OFF_S0 0
#define OFF_D0 (NSRC0)
#define OFF_S1 (NSRC0 + NDST0)
#define OFF_D1 (NSRC0 + 2 * NDST0)
#define CNT_TOTAL (NSRC0 + 2 * NDST0 + NDST1)

// ---------------- scratch (device globals; no allocations) ----------------
__device__ float g_X[(size_t)NSRC0 * FEAT];      // node-major src features (unscaled)
__device__ float g_h0[(size_t)NDST0 * FEAT];     // layer-0 output * ns1

__device__ int g_cnt[CNT_TOTAL];                 // [s0 | d0 | s1 | d1] degrees
__device__ float g_ns0[NSRC0];
__device__ float g_nd0[NDST0];
__device__ float g_ns1[NDST0];
__device__ float g_nd1[NDST1];

__device__ int g_off0[NDST0 + 1];
__device__ int g_cur0[NDST0];
__device__ int g_csr0[E0];     // src ids grouped by dst
__device__ int g_off1[NDST1 + 1];
__device__ int g_cur1[NDST1];
__device__ int g_csr1[E1];

// ---------------- degree histogram (counts zeroed by memsetAsync) ----------------
__global__ void k_hist(const int* __restrict__ s0, const int* __restrict__ d0,
                       const int* __restrict__ s1, const int* __restrict__ d1) {
    int i = blockIdx.x * blockDim.x + threadIdx.x;
    if (i < E0) {
        atomicAdd(&g_cnt[OFF_S0 + s0[i]], 1);
        atomicAdd(&g_cnt[OFF_D0 + d0[i]], 1);
    }
    if (i < E1) {
        atomicAdd(&g_cnt[OFF_S1 + s1[i]], 1);
        atomicAdd(&g_cnt[OFF_D1 + d1[i]], 1);
    }
}

// ---------------- scan (blocks 0,1) + norms (blocks 2+), all after hist ----------------
__global__ void __launch_bounds__(1024) k_prep() {
    int bid = blockIdx.x;
    if (bid < 2) {
        const int* cnt; int* off; int* cur; int n;
        if (bid == 0) { cnt = g_cnt + OFF_D0; off = g_off0; cur = g_cur0; n = NDST0; }
        else          { cnt = g_cnt + OFF_D1; off = g_off1; cur = g_cur1; n = NDST1; }
        int t = threadIdx.x;
        int per = (n + 1023) >> 10;
        int base = t * per;
        int s = 0;
        for (int i = 0; i < per; i++)
            if (base + i < n) s += cnt[base + i];
        int lane = t & 31, wid = t >> 5;
        int v = s;
        #pragma unroll
        for (int d = 1; d < 32; d <<= 1) {
            int x = __shfl_up_sync(~0u, v, d);
            if (lane >= d) v += x;
        }
        __shared__ int wsum[32];
        if (lane == 31) wsum[wid] = v;
        __syncthreads();
        if (wid == 0) {
            int wv = wsum[lane];
            #pragma unroll
            for (int d = 1; d < 32; d <<= 1) {
                int x = __shfl_up_sync(~0u, wv, d);
                if (lane >= d) wv += x;
            }
            wsum[lane] = wv;
        }
        __syncthreads();
        int run = v - s + (wid ? wsum[wid - 1] : 0);   // exclusive prefix of this chunk
        for (int i = 0; i < per; i++) {
            int idx = base + i;
            if (idx < n) { off[idx] = run; cur[idx] = run; run += cnt[idx]; }
        }
        if (t == 1023) off[n] = run;                   // = grand total
    } else {
        int i = (bid - 2) * 1024 + threadIdx.x;
        if (i < NSRC0) g_ns0[i] = rsqrtf((float)max(g_cnt[OFF_S0 + i], 1));
        if (i < NDST0) {
            g_nd0[i] = rsqrtf((float)max(g_cnt[OFF_D0 + i], 1));
            g_ns1[i] = rsqrtf((float)max(g_cnt[OFF_S1 + i], 1));
        }
        if (i < NDST1) g_nd1[i] = rsqrtf((float)max(g_cnt[OFF_D1 + i], 1));
    }
}

__global__ void k_fill(const int* __restrict__ s0, const int* __restrict__ d0,
                       const int* __restrict__ s1, const int* __restrict__ d1) {
    int i = blockIdx.x * blockDim.x + threadIdx.x;
    if (i < E0) { int p = atomicAdd(&g_cur0[d0[i]], 1); g_csr0[p] = s0[i]; }
    if (i < E1) { int p = atomicAdd(&g_cur1[d1[i]], 1); g_csr1[p] = s1[i]; }
}

// ---------------- input transpose [A,H,C,N] -> X[n][(a*2+c)*128+h] (no scaling) ----------------
__global__ void k_transpose(const float* __restrict__ inf) {
    __shared__ float sh[64][33];
    int fi0 = blockIdx.y * 64;        // 0..448 step 64
    int n0  = blockIdx.x * 32;
    int tx = threadIdx.x;             // 32
    int ty = threadIdx.y;             // 16
    int n = n0 + tx;
    bool nok = n < NSRC0;
    #pragma unroll
    for (int r = ty; r < 64; r += 16)
        sh[r][tx] = nok ? inf[(size_t)(fi0 + r) * NSRC0 + n] : 0.f;
    __syncthreads();
    int a  = fi0 >> 8;
    int h0 = (fi0 & 255) >> 1;
    #pragma unroll
    for (int c = 0; c < 2; c++) {
        for (int nn = ty; nn < 32; nn += 16) {
            int nidx = n0 + nn;
            if (nidx < NSRC0)
                g_X[(size_t)nidx * FEAT + a * 256 + c * 128 + h0 + tx] = sh[tx * 2 + c][nn];
        }
    }
}

// ---------------- fused aggregate + GEMM (+ optional transposed output) ----------------
// Block = 32 dst nodes = 128 A-rows. Phase A: 8 warps gather/sum neighbor rows
// (scaled by ns[src] if ns != null) into smem A-tile. Phase B: 128x128x128 GEMM
// with packed f32x2 FMA. Epilogue: *nd[node] + b, relu, *s2[node]; written either
// row-major to Crow, or feature-major transposed to Ctr (final output).
#define SA 132
__global__ void __launch_bounds__(256, 1)
k_fused(const int* __restrict__ off, const int* __restrict__ csr,
        const float* __restrict__ feat, const float* __restrict__ ns,
        const float* __restrict__ Wm, const float* __restrict__ bias,
        const float* __restrict__ nd, const float* __restrict__ s2,
        float* __restrict__ Crow, float* __restrict__ Ctr) {
    extern __shared__ float sh[];
    float* Ash = sh;                 // [128][SA]
    float* Ws  = sh + 128 * SA;      // [128][SA]
    float* bs  = sh + 2 * 128 * SA;  // [128]
    int tid = threadIdx.x;
    int wid = tid >> 5, lane = tid & 31;
    int node0 = blockIdx.x * 32;

    // W + bias into smem (issues early, overlaps with the gather below)
    #pragma unroll 4
    for (int i = tid; i < 4096; i += 256) {
        int k = i >> 5, c4 = i & 31;
        *(float4*)(Ws + k * SA + c4 * 4) = *((const float4*)(Wm + k * Hd) + c4);
    }
    if (tid < 128) bs[tid] = bias[tid];

    // Phase A: warp wid aggregates local nodes wid*4 .. wid*4+3
    #pragma unroll
    for (int t2 = 0; t2 < 4; t2++) {
        int ln = wid * 4 + t2;
        int node = node0 + ln;
        int beg = off[node], end = off[node + 1];
        float4 a0 = make_float4(0.f, 0.f, 0.f, 0.f), a1 = a0, a2 = a0, a3 = a0;
        int e = beg;
        for (; e + 1 < end; e += 2) {
            int sA = csr[e], sB = csr[e + 1];
            float wA = ns ? ns[sA] : 1.f;
            float wB = ns ? ns[sB] : 1.f;
            const float4* pA = (const float4*)(feat + (size_t)sA * FEAT) + lane;
            const float4* pB = (const float4*)(feat + (size_t)sB * FEAT) + lane;
            float4 v0 = pA[0], v1 = pA[32], v2 = pA[64], v3 = pA[96];
            float4 u0 = pB[0], u1 = pB[32], u2 = pB[64], u3 = pB[96];
            a0.x += wA * v0.x + wB * u0.x; a0.y += wA * v0.y + wB * u0.y;
            a0.z += wA * v0.z + wB * u0.z; a0.w += wA * v0.w + wB * u0.w;
            a1.x += wA * v1.x + wB * u1.x; a1.y += wA * v1.y + wB * u1.y;
            a1.z += wA * v1.z + wB * u1.z; a1.w += wA * v1.w + wB * u1.w;
            a2.x += wA * v2.x + wB * u2.x; a2.y += wA * v2.y + wB * u2.y;
            a2.z += wA * v2.z + wB * u2.z; a2.w += wA * v2.w + wB * u2.w;
            a3.x += wA * v3.x + wB * u3.x; a3.y += wA * v3.y + wB * u3.y;
            a3.z += wA * v3.z + wB * u3.z; a3.w += wA * v3.w + wB * u3.w;
        }
        if (e < end) {
            int sA = csr[e];
            float wA = ns ? ns[sA] : 1.f;
            const float4* pA = (const float4*)(feat + (size_t)sA * FEAT) + lane;
            float4 v0 = pA[0], v1 = pA[32], v2 = pA[64], v3 = pA[96];
            a0.x += wA * v0.x; a0.y += wA * v0.y; a0.z += wA * v0.z; a0.w += wA * v0.w;
            a1.x += wA * v1.x; a1.y += wA * v1.y; a1.z += wA * v1.z; a1.w += wA * v1.w;
            a2.x += wA * v2.x; a2.y += wA * v2.y; a2.z += wA * v2.z; a2.w += wA * v2.w;
            a3.x += wA * v3.x; a3.y += wA * v3.y; a3.z += wA * v3.z; a3.w += wA * v3.w;
        }
        // row r = ln*4 + g  holds features g*128 + [0..127]
        *(float4*)(Ash + (ln * 4 + 0) * SA + lane * 4) = a0;
        *(float4*)(Ash + (ln * 4 + 1) * SA + lane * 4) = a1;
        *(float4*)(Ash + (ln * 4 + 2) * SA + lane * 4) = a2;
        *(float4*)(Ash + (ln * 4 + 3) * SA + lane * 4) = a3;
    }
    __syncthreads();

    // Phase B: GEMM. 4x16 microtile per thread.
    int rowgrp = tid >> 3;   // 0..31 -> rows rowgrp*4 .. +3
    int colgrp = tid & 7;    // 0..7  -> float4 cols {j*8+colgrp}

    unsigned long long acc[4][8];
    #pragma unroll
    for (int i = 0; i < 4; i++)
        #pragma unroll
        for (int j = 0; j < 8; j++) acc[i][j] = 0ull;

    #pragma unroll 4
    for (int k = 0; k < 128; k++) {
        unsigned long long ap[4];
        #pragma unroll
        for (int i = 0; i < 4; i++) {
            float av = Ash[(rowgrp * 4 + i) * SA + k];
            asm("mov.b64 %0, {%1, %1};" : "=l"(ap[i]) : "f"(av));
        }
        ulonglong2 wv[4];
        #pragma unroll
        for (int j = 0; j < 4; j++)
            wv[j] = *(const ulonglong2*)(Ws + k * SA + (j * 8 + colgrp) * 4);
        #pragma unroll
        for (int i = 0; i < 4; i++) {
            #pragma unroll
            for (int j = 0; j < 4; j++) {
                asm("fma.rn.f32x2 %0, %1, %2, %0;" : "+l"(acc[i][2 * j])     : "l"(ap[i]), "l"(wv[j].x));
                asm("fma.rn.f32x2 %0, %1, %2, %0;" : "+l"(acc[i][2 * j + 1]) : "l"(ap[i]), "l"(wv[j].y));
            }
        }
    }

    if (Ctr == nullptr) {
        // row-major epilogue -> Crow
        #pragma unroll
        for (int i = 0; i < 4; i++) {
            int r = rowgrp * 4 + i;
            int node = node0 + (r >> 2);
            float scale = nd[node];
            float s2v = s2 ? s2[node] : 1.f;
            size_t grow = (size_t)node0 * 4 + r;
            #pragma unroll
            for (int j = 0; j < 4; j++) {
                int c4 = j * 8 + colgrp;
                float4 o;
                asm("mov.b64 {%0, %1}, %2;" : "=f"(o.x), "=f"(o.y) : "l"(acc[i][2 * j]));
                asm("mov.b64 {%0, %1}, %2;" : "=f"(o.z), "=f"(o.w) : "l"(acc[i][2 * j + 1]));
                float4 bb = *(const float4*)(bs + c4 * 4);
                o.x = fmaxf(o.x * scale + bb.x, 0.f) * s2v;
                o.y = fmaxf(o.y * scale + bb.y, 0.f) * s2v;
                o.z = fmaxf(o.z * scale + bb.z, 0.f) * s2v;
                o.w = fmaxf(o.w * scale + bb.w, 0.f) * s2v;
                *(float4*)(Crow + grow * Hd + c4 * 4) = o;
            }
        }
    } else {
        // transposed epilogue: relu'd values -> Fsh[f][node] -> out[a][h][c][n]
        __syncthreads();                 // everyone done reading Ash
        float* Fsh = Ash;                // reuse as [512][33] (512*33 = 128*132)
        #pragma unroll
        for (int i = 0; i < 4; i++) {
            int r = rowgrp * 4 + i;
            int ln = r >> 2, g = r & 3;
            int node = node0 + ln;
            float scale = nd[node];
            #pragma unroll
            for (int j = 0; j < 4; j++) {
                int c4 = j * 8 + colgrp;
                float4 o;
                asm("mov.b64 {%0, %1}, %2;" : "=f"(o.x), "=f"(o.y) : "l"(acc[i][2 * j]));
                asm("mov.b64 {%0, %1}, %2;" : "=f"(o.z), "=f"(o.w) : "l"(acc[i][2 * j + 1]));
                float4 bb = *(const float4*)(bs + c4 * 4);
                int fb = g * 128 + c4 * 4;
                Fsh[(fb + 0) * 33 + ln] = fmaxf(o.x * scale + bb.x, 0.f);
                Fsh[(fb + 1) * 33 + ln] = fmaxf(o.y * scale + bb.y, 0.f);
                Fsh[(fb + 2) * 33 + ln] = fmaxf(o.z * scale + bb.z, 0.f);
                Fsh[(fb + 3) * 33 + ln] = fmaxf(o.w * scale + bb.w, 0.f);
            }
        }
        __syncthreads();
        // f = a*256 + c*128 + h  ->  out[(a*128+h)*2 + c][node]
        for (int f = tid >> 5; f < FEAT; f += 8) {
            int g = f >> 7, h = f & 127;
            int a = g >> 1, c = g & 1;
            int fo = (a * 128 + h) * 2 + c;
            Ctr[(size_t)fo * NDST1 + node0 + lane] = Fsh[f * 33 + lane];
        }
    }
}

// ---------------- launcher ----------------
extern "C" void kernel_launch(void* const* d_in, const int* in_sizes, int n_in,
                              void* d_out, int out_size) {
    const float* in_feat = (const float*)d_in[0];
    const float* W       = (const float*)d_in[1];
    const float* b       = (const float*)d_in[2];
    const int* e0s = (const int*)d_in[3];
    const int* e0d = (const int*)d_in[4];
    const int* e1s = (const int*)d_in[5];
    const int* e1d = (const int*)d_in[6];
    float* out = (float*)d_out;

    void *pX, *ph0, *pcnt;
    void *poff0, *pcsr0, *poff1, *pcsr1;
    void *pns0, *pnd0, *pns1, *pnd1;
    cudaGetSymbolAddress(&pX, g_X);
    cudaGetSymbolAddress(&ph0, g_h0);
    cudaGetSymbolAddress(&pcnt, g_cnt);
    cudaGetSymbolAddress(&poff0, g_off0);
    cudaGetSymbolAddress(&pcsr0, g_csr0);
    cudaGetSymbolAddress(&poff1, g_off1);
    cudaGetSymbolAddress(&pcsr1, g_csr1);
    cudaGetSymbolAddress(&pns0, g_ns0);
    cudaGetSymbolAddress(&pnd0, g_nd0);
    cudaGetSymbolAddress(&pns1, g_ns1);
    cudaGetSymbolAddress(&pnd1, g_nd1);

    int smem_bytes = (2 * 128 * SA + 128) * (int)sizeof(float);
    cudaFuncSetAttribute(k_fused, cudaFuncAttributeMaxDynamicSharedMemorySize, smem_bytes);

    // 1. degrees + norms + CSR
    cudaMemsetAsync(pcnt, 0, CNT_TOTAL * sizeof(int));
    k_hist<<<(E0 + 255) / 256, 256>>>(e0s, e0d, e1s, e1d);
    k_prep<<<2 + (NSRC0 + 1023) / 1024, 1024>>>();
    k_fill<<<(E0 + 255) / 256, 256>>>(e0s, e0d, e1s, e1d);

    // 2. transpose input (raw, ns0 applied during aggregation)
    {
        dim3 gr((NSRC0 + 31) / 32, FEAT / 64);
        dim3 bl(32, 16);
        k_transpose<<<gr, bl>>>(in_feat);
    }

    // 3. layer 0 fused: agg(*ns0) -> GEMM(*nd0 + b, relu, *ns1) -> h0
    k_fused<<<NDST0 / 32, 256, smem_bytes>>>(
        (const int*)poff0, (const int*)pcsr0, (const float*)pX, (const float*)pns0,
        W, b, (const float*)pnd0, (const float*)pns1, (float*)ph0, nullptr);

    // 4. layer 1 fused: agg -> GEMM(*nd1 + b, relu) -> transposed out
    k_fused<<<NDST1 / 32, 256, smem_bytes>>>(
        (const int*)poff1, (const int*)pcsr1, (const float*)ph0, (const float*)nullptr,
        W, b, (const float*)pnd1, (const float*)nullptr, nullptr, out);

    (void)in_sizes; (void)n_in; (void)out_size;
}

// round 5
// speedup vs baseline: 1.3217x; 1.3217x over previous
#include <cuda_runtime.h>
#include <cstdint>
#include <cstddef>

#define Hd 128
#define FEAT 512
#define NSRC0 50000
#define NDST0 20000
#define NDST1 4096
#define E0 320000
#define E1 65536

#define OFF_S0 0
#define OFF_D0 (NSRC0)
#define OFF_S1 (NSRC0 + NDST0)
#define OFF_D1 (NSRC0 + 2 * NDST0)
#define CNT_TOTAL (NSRC0 + 2 * NDST0 + NDST1)

// ---------------- scratch (device globals; no allocations) ----------------
__device__ float g_X[(size_t)NSRC0 * FEAT];      // node-major src features * ns0
__device__ float g_agg0[(size_t)NDST0 * FEAT];
__device__ float g_h0[(size_t)NDST0 * FEAT];     // layer-0 output * ns1
__device__ float g_agg1[(size_t)NDST1 * FEAT];

__device__ int g_cnt[CNT_TOTAL];                 // [s0 | d0 | s1 | d1] degrees
__device__ float g_ns0[NSRC0];
__device__ float g_nd0[NDST0];
__device__ float g_ns1[NDST0];
__device__ float g_nd1[NDST1];

__device__ int g_off0[NDST0 + 1];
__device__ int g_cur0[NDST0];
__device__ int g_csr0[E0];
__device__ int g_off1[NDST1 + 1];
__device__ int g_cur1[NDST1];
__device__ int g_csr1[E1];

// ---------------- degree histogram (counts zeroed by memsetAsync) ----------------
__global__ void k_hist(const int* __restrict__ s0, const int* __restrict__ d0,
                       const int* __restrict__ s1, const int* __restrict__ d1) {
    int i = blockIdx.x * blockDim.x + threadIdx.x;
    if (i < E0) {
        atomicAdd(&g_cnt[OFF_S0 + s0[i]], 1);
        atomicAdd(&g_cnt[OFF_D0 + d0[i]], 1);
    }
    if (i < E1) {
        atomicAdd(&g_cnt[OFF_S1 + s1[i]], 1);
        atomicAdd(&g_cnt[OFF_D1 + d1[i]], 1);
    }
}

// ---------------- scan (blocks 0,1) + norms (blocks 2+) ----------------
__global__ void __launch_bounds__(1024) k_prep() {
    int bid = blockIdx.x;
    if (bid < 2) {
        const int* cnt; int* off; int* cur; int n;
        if (bid == 0) { cnt = g_cnt + OFF_D0; off = g_off0; cur = g_cur0; n = NDST0; }
        else          { cnt = g_cnt + OFF_D1; off = g_off1; cur = g_cur1; n = NDST1; }
        int t = threadIdx.x;
        int per = (n + 1023) >> 10;
        int base = t * per;
        int s = 0;
        for (int i = 0; i < per; i++)
            if (base + i < n) s += cnt[base + i];
        int lane = t & 31, wid = t >> 5;
        int v = s;
        #pragma unroll
        for (int d = 1; d < 32; d <<= 1) {
            int x = __shfl_up_sync(~0u, v, d);
            if (lane >= d) v += x;
        }
        __shared__ int wsum[32];
        if (lane == 31) wsum[wid] = v;
        __syncthreads();
        if (wid == 0) {
            int wv = wsum[lane];
            #pragma unroll
            for (int d = 1; d < 32; d <<= 1) {
                int x = __shfl_up_sync(~0u, wv, d);
                if (lane >= d) wv += x;
            }
            wsum[lane] = wv;
        }
        __syncthreads();
        int run = v - s + (wid ? wsum[wid - 1] : 0);
        for (int i = 0; i < per; i++) {
            int idx = base + i;
            if (idx < n) { off[idx] = run; cur[idx] = run; run += cnt[idx]; }
        }
        if (t == 1023) off[n] = run;
    } else {
        int i = (bid - 2) * 1024 + threadIdx.x;
        if (i < NSRC0) g_ns0[i] = rsqrtf((float)max(g_cnt[OFF_S0 + i], 1));
        if (i < NDST0) {
            g_nd0[i] = rsqrtf((float)max(g_cnt[OFF_D0 + i], 1));
            g_ns1[i] = rsqrtf((float)max(g_cnt[OFF_S1 + i], 1));
        }
        if (i < NDST1) g_nd1[i] = rsqrtf((float)max(g_cnt[OFF_D1 + i], 1));
    }
}

__global__ void k_fill(const int* __restrict__ s0, const int* __restrict__ d0,
                       const int* __restrict__ s1, const int* __restrict__ d1) {
    int i = blockIdx.x * blockDim.x + threadIdx.x;
    if (i < E0) { int p = atomicAdd(&g_cur0[d0[i]], 1); g_csr0[p] = s0[i]; }
    if (i < E1) { int p = atomicAdd(&g_cur1[d1[i]], 1); g_csr1[p] = s1[i]; }
}

// ---------------- vectorized input transpose ----------------
// [A,H,C,N] -> X[n][(a*2+c)*128+h], * ns0[n]. Tile: 64 features x 128 nodes.
// float4 on both GMEM sides; smem pad 129 (2-way LDS conflicts only).
#define TP 129
__global__ void __launch_bounds__(256) k_transpose(const float* __restrict__ inf) {
    __shared__ float sm[64 * TP];
    int fi0 = blockIdx.y * 64;
    int n0  = blockIdx.x * 128;
    int tid = threadIdx.x;

    // load: 64 features x 32 float4 = 2048 float4, 8 per thread
    #pragma unroll
    for (int i = 0; i < 8; i++) {
        int idx = i * 256 + tid;
        int f = idx >> 5;          // 0..63
        int v = idx & 31;          // float4 along n
        int n = n0 + v * 4;
        if (n < NSRC0) {           // NSRC0 % 4 == 0, no straddle
            float4 x = *(const float4*)(inf + (size_t)(fi0 + f) * NSRC0 + n);
            sm[f * TP + v * 4 + 0] = x.x;
            sm[f * TP + v * 4 + 1] = x.y;
            sm[f * TP + v * 4 + 2] = x.z;
            sm[f * TP + v * 4 + 3] = x.w;
        }
    }
    __syncthreads();

    int a  = fi0 >> 8;
    int h0 = (fi0 & 255) >> 1;
    // store: 128 nodes x 2 c x 8 float4(along h) = 2048 float4, 8 per thread
    #pragma unroll
    for (int i = 0; i < 8; i++) {
        int idx = i * 256 + tid;
        int ln = idx >> 4;          // node 0..127
        int rest = idx & 15;
        int c = rest >> 3;
        int q = rest & 7;           // float4 index along h
        int n = n0 + ln;
        if (n < NSRC0) {
            float s = g_ns0[n];
            float4 o;
            int fb = (q * 4) * 2 + c;    // local feature of first lane: (h-h0)*2+c
            o.x = sm[(fb + 0) * TP + ln] * s;
            o.y = sm[(fb + 2) * TP + ln] * s;
            o.z = sm[(fb + 4) * TP + ln] * s;
            o.w = sm[(fb + 6) * TP + ln] * s;
            *(float4*)(g_X + (size_t)n * FEAT + a * 256 + c * 128 + h0 + q * 4) = o;
        }
    }
}

// ---------------- aggregation: warp per dst, full 512-f row ----------------
__global__ void k_agg(const int* __restrict__ off, const int* __restrict__ csr,
                      const float* __restrict__ feat, float* __restrict__ out, int ndst) {
    int w = (blockIdx.x * blockDim.x + threadIdx.x) >> 5;
    int lane = threadIdx.x & 31;
    if (w >= ndst) return;
    int beg = off[w], end = off[w + 1];
    float4 a0 = make_float4(0.f, 0.f, 0.f, 0.f), a1 = a0, a2 = a0, a3 = a0;
    for (int e = beg; e < end; e++) {
        const float4* p = (const float4*)(feat + (size_t)csr[e] * FEAT) + lane;
        float4 v0 = p[0], v1 = p[32], v2 = p[64], v3 = p[96];
        a0.x += v0.x; a0.y += v0.y; a0.z += v0.z; a0.w += v0.w;
        a1.x += v1.x; a1.y += v1.y; a1.z += v1.z; a1.w += v1.w;
        a2.x += v2.x; a2.y += v2.y; a2.z += v2.z; a2.w += v2.w;
        a3.x += v3.x; a3.y += v3.y; a3.z += v3.z; a3.w += v3.w;
    }
    float4* o = (float4*)(out + (size_t)w * FEAT) + lane;
    o[0] = a0; o[32] = a1; o[64] = a2; o[96] = a3;
}

// ---------------- GEMM: 128-row blocks, 256 threads, 4x16 microtile, f32x2 FMA ----------------
// Epilogue: *nd[node] + b, relu, *s2[node]; row-major to Crow OR transposed to Ctr.
#define SA 132
__global__ void __launch_bounds__(256, 1)
k_gemm(const float* __restrict__ A, const float* __restrict__ Wm,
       const float* __restrict__ bias, const float* __restrict__ nd,
       const float* __restrict__ s2, float* __restrict__ Crow, float* __restrict__ Ctr) {
    extern __shared__ float sh[];
    float* Ash = sh;                 // [128][SA]
    float* Ws  = sh + 128 * SA;      // [128][SA]
    float* bs  = sh + 2 * 128 * SA;  // [128]
    int tid = threadIdx.x;
    int node0 = blockIdx.x * 32;
    size_t row0 = (size_t)blockIdx.x * 128;

    #pragma unroll 4
    for (int i = tid; i < 4096; i += 256) {
        int r = i >> 5, k4 = i & 31;
        float4 v = *((const float4*)(A + (row0 + r) * Hd) + k4);
        *(float4*)(Ash + r * SA + k4 * 4) = v;
    }
    #pragma unroll 4
    for (int i = tid; i < 4096; i += 256) {
        int k = i >> 5, c4 = i & 31;
        *(float4*)(Ws + k * SA + c4 * 4) = *((const float4*)(Wm + k * Hd) + c4);
    }
    if (tid < 128) bs[tid] = bias[tid];
    __syncthreads();

    int rowgrp = tid >> 3;
    int colgrp = tid & 7;

    unsigned long long acc[4][8];
    #pragma unroll
    for (int i = 0; i < 4; i++)
        #pragma unroll
        for (int j = 0; j < 8; j++) acc[i][j] = 0ull;

    #pragma unroll 4
    for (int k = 0; k < 128; k++) {
        unsigned long long ap[4];
        #pragma unroll
        for (int i = 0; i < 4; i++) {
            float av = Ash[(rowgrp * 4 + i) * SA + k];
            asm("mov.b64 %0, {%1, %1};" : "=l"(ap[i]) : "f"(av));
        }
        ulonglong2 wv[4];
        #pragma unroll
        for (int j = 0; j < 4; j++)
            wv[j] = *(const ulonglong2*)(Ws + k * SA + (j * 8 + colgrp) * 4);
        #pragma unroll
        for (int i = 0; i < 4; i++) {
            #pragma unroll
            for (int j = 0; j < 4; j++) {
                asm("fma.rn.f32x2 %0, %1, %2, %0;" : "+l"(acc[i][2 * j])     : "l"(ap[i]), "l"(wv[j].x));
                asm("fma.rn.f32x2 %0, %1, %2, %0;" : "+l"(acc[i][2 * j + 1]) : "l"(ap[i]), "l"(wv[j].y));
            }
        }
    }

    if (Ctr == nullptr) {
        #pragma unroll
        for (int i = 0; i < 4; i++) {
            int r = rowgrp * 4 + i;
            int node = node0 + (r >> 2);
            float scale = nd[node];
            float s2v = s2 ? s2[node] : 1.f;
            size_t grow = row0 + r;
            #pragma unroll
            for (int j = 0; j < 4; j++) {
                int c4 = j * 8 + colgrp;
                float4 o;
                asm("mov.b64 {%0, %1}, %2;" : "=f"(o.x), "=f"(o.y) : "l"(acc[i][2 * j]));
                asm("mov.b64 {%0, %1}, %2;" : "=f"(o.z), "=f"(o.w) : "l"(acc[i][2 * j + 1]));
                float4 bb = *(const float4*)(bs + c4 * 4);
                o.x = fmaxf(o.x * scale + bb.x, 0.f) * s2v;
                o.y = fmaxf(o.y * scale + bb.y, 0.f) * s2v;
                o.z = fmaxf(o.z * scale + bb.z, 0.f) * s2v;
                o.w = fmaxf(o.w * scale + bb.w, 0.f) * s2v;
                *(float4*)(Crow + grow * Hd + c4 * 4) = o;
            }
        }
    } else {
        __syncthreads();                 // done reading Ash
        float* Fsh = Ash;                // reuse as [512][33]
        #pragma unroll
        for (int i = 0; i < 4; i++) {
            int r = rowgrp * 4 + i;
            int ln = r >> 2, g = r & 3;
            int node = node0 + ln;
            float scale = nd[node];
            #pragma unroll
            for (int j = 0; j < 4; j++) {
                int c4 = j * 8 + colgrp;
                float4 o;
                asm("mov.b64 {%0, %1}, %2;" : "=f"(o.x), "=f"(o.y) : "l"(acc[i][2 * j]));
                asm("mov.b64 {%0, %1}, %2;" : "=f"(o.z), "=f"(o.w) : "l"(acc[i][2 * j + 1]));
                float4 bb = *(const float4*)(bs + c4 * 4);
                int fb = g * 128 + c4 * 4;
                Fsh[(fb + 0) * 33 + ln] = fmaxf(o.x * scale + bb.x, 0.f);
                Fsh[(fb + 1) * 33 + ln] = fmaxf(o.y * scale + bb.y, 0.f);
                Fsh[(fb + 2) * 33 + ln] = fmaxf(o.z * scale + bb.z, 0.f);
                Fsh[(fb + 3) * 33 + ln] = fmaxf(o.w * scale + bb.w, 0.f);
            }
        }
        __syncthreads();
        int lane = tid & 31;
        for (int f = tid >> 5; f < FEAT; f += 8) {
            int g = f >> 7, h = f & 127;
            int a = g >> 1, c = g & 1;
            int fo = (a * 128 + h) * 2 + c;
            Ctr[(size_t)fo * NDST1 + node0 + lane] = Fsh[f * 33 + lane];
        }
    }
}

// ---------------- launcher ----------------
extern "C" void kernel_launch(void* const* d_in, const int* in_sizes, int n_in,
                              void* d_out, int out_size) {
    const float* in_feat = (const float*)d_in[0];
    const float* W       = (const float*)d_in[1];
    const float* b       = (const float*)d_in[2];
    const int* e0s = (const int*)d_in[3];
    const int* e0d = (const int*)d_in[4];
    const int* e1s = (const int*)d_in[5];
    const int* e1d = (const int*)d_in[6];
    float* out = (float*)d_out;

    void *pX, *pagg0, *ph0, *pagg1, *pcnt;
    void *poff0, *pcsr0, *poff1, *pcsr1;
    void *pnd0, *pns1, *pnd1;
    cudaGetSymbolAddress(&pX, g_X);
    cudaGetSymbolAddress(&pagg0, g_agg0);
    cudaGetSymbolAddress(&ph0, g_h0);
    cudaGetSymbolAddress(&pagg1, g_agg1);
    cudaGetSymbolAddress(&pcnt, g_cnt);
    cudaGetSymbolAddress(&poff0, g_off0);
    cudaGetSymbolAddress(&pcsr0, g_csr0);
    cudaGetSymbolAddress(&poff1, g_off1);
    cudaGetSymbolAddress(&pcsr1, g_csr1);
    cudaGetSymbolAddress(&pnd0, g_nd0);
    cudaGetSymbolAddress(&pns1, g_ns1);
    cudaGetSymbolAddress(&pnd1, g_nd1);

    int smem_bytes = (2 * 128 * SA + 128) * (int)sizeof(float);
    cudaFuncSetAttribute(k_gemm, cudaFuncAttributeMaxDynamicSharedMemorySize, smem_bytes);

    // 1. degrees + norms + CSR
    cudaMemsetAsync(pcnt, 0, CNT_TOTAL * sizeof(int));
    k_hist<<<(E0 + 255) / 256, 256>>>(e0s, e0d, e1s, e1d);
    k_prep<<<2 + (NSRC0 + 1023) / 1024, 1024>>>();
    k_fill<<<(E0 + 255) / 256, 256>>>(e0s, e0d, e1s, e1d);

    // 2. transpose input (fold ns0), float4 both sides
    {
        dim3 gr((NSRC0 + 127) / 128, FEAT / 64);
        k_transpose<<<gr, 256>>>(in_feat);
    }

    // 3. layer 0: agg -> GEMM(*nd0 + b, relu, *ns1)
    k_agg<<<(NDST0 + 7) / 8, 256>>>((const int*)poff0, (const int*)pcsr0,
                                    (const float*)pX, (float*)pagg0, NDST0);
    k_gemm<<<NDST0 * 4 / 128, 256, smem_bytes>>>((const float*)pagg0, W, b,
                                                 (const float*)pnd0, (const float*)pns1,
                                                 (float*)ph0, nullptr);

    // 4. layer 1: agg -> GEMM(*nd1 + b, relu) -> transposed out
    k_agg<<<(NDST1 + 7) / 8, 256>>>((const int*)poff1, (const int*)pcsr1,
                                    (const float*)ph0, (float*)pagg1, NDST1);
    k_gemm<<<NDST1 * 4 / 128, 256, smem_bytes>>>((const float*)pagg1, W, b,
                                                 (const float*)pnd1, (const float*)nullptr,
                                                 nullptr, out);

    (void)in_sizes; (void)n_in; (void)out_size;
}